// round 1
// baseline (speedup 1.0000x reference)
#include <cuda_runtime.h>

#define DEGREE   6
#define WIDTH    7          // DEGREE - START_DEGREE + 1
#define FEAT     1024       // in_features
#define OUTF     1024       // out_features
#define THREADS  256

// Fused kernel: one block per batch row.
// Phase 1: each thread handles 4 features (float4), computes the 7 Hermite
//          basis partial sums; block-reduce to basis[7] in shared.
// Phase 2: each thread computes 4 outputs (float4 store) from basis[7] and
//          its 28 contiguous coeffs (7x LDG.128, L1-hot after first block/SM).
__global__ __launch_bounds__(THREADS)
void hermite_fused_kernel(const float* __restrict__ x,
                          const float* __restrict__ coeffs,
                          const float* __restrict__ sigma,
                          float* __restrict__ out)
{
    __shared__ float s_part[(THREADS / 32) * WIDTH];
    __shared__ float s_basis[WIDTH];

    const int b   = blockIdx.x;
    const int tid = threadIdx.x;

    const float s     = fminf(fmaxf(sigma[0], 0.1f), 5.0f);
    const float inv_s = 1.0f / s;

    // ---- Phase 1: per-thread partial basis sums over 4 features ----
    const float4 xv =
        reinterpret_cast<const float4*>(x + (size_t)b * FEAT)[tid];
    const float xe[4] = { xv.x, xv.y, xv.z, xv.w };

    float acc[WIDTH];
#pragma unroll
    for (int w = 0; w < WIDTH; ++w) acc[w] = 0.0f;

#pragma unroll
    for (int e = 0; e < 4; ++e) {
        const float xs = xe[e] * inv_s;
        const float t  = fminf(xs * xs, 50.0f);
        const float g  = __expf(-t);

        float hm2 = 1.0f;          // H0
        float hm1 = 2.0f * xs;     // H1 (unclipped, as in reference)
        acc[0] += g * hm2;
        acc[1] += g * hm1;

        const float two_xs = 2.0f * xs;
#pragma unroll
        for (int n = 2; n <= DEGREE; ++n) {
            float h = two_xs * hm1 - (2.0f * (float)(n - 1)) * hm2;
            h = fminf(fmaxf(h, -100.0f), 100.0f);   // clip BEFORE recursion use
            acc[n] += g * h;
            hm2 = hm1;
            hm1 = h;
        }
    }

    // ---- Block reduction of the 7 accumulators ----
#pragma unroll
    for (int w = 0; w < WIDTH; ++w) {
#pragma unroll
        for (int off = 16; off > 0; off >>= 1)
            acc[w] += __shfl_xor_sync(0xffffffffu, acc[w], off);
    }
    const int lane = tid & 31;
    const int warp = tid >> 5;
    if (lane == 0) {
#pragma unroll
        for (int w = 0; w < WIDTH; ++w)
            s_part[warp * WIDTH + w] = acc[w];
    }
    __syncthreads();

    if (tid < WIDTH) {
        float v = 0.0f;
#pragma unroll
        for (int w = 0; w < (THREADS / 32); ++w)
            v += s_part[w * WIDTH + tid];
        s_basis[tid] = v;
    }
    __syncthreads();

    float basis[WIDTH];
#pragma unroll
    for (int w = 0; w < WIDTH; ++w) basis[w] = s_basis[w];

    // ---- Phase 2: 4 outputs per thread ----
    // Thread tid owns outputs [4*tid, 4*tid+3]; its 28 coeffs are contiguous
    // (28 floats = 112 B, 16B-aligned) -> 7x vectorized loads.
    const int o0 = tid * 4;
    const float4* c4 =
        reinterpret_cast<const float4*>(coeffs + (size_t)o0 * WIDTH);
    float4 c[7];
#pragma unroll
    for (int i = 0; i < 7; ++i) c[i] = c4[i];
    const float* cf = reinterpret_cast<const float*>(c);

    float4 r;
    float* rp = reinterpret_cast<float*>(&r);
#pragma unroll
    for (int i = 0; i < 4; ++i) {
        float v = 0.0f;
#pragma unroll
        for (int w = 0; w < WIDTH; ++w)
            v += basis[w] * cf[i * WIDTH + w];
        rp[i] = v;
    }
    reinterpret_cast<float4*>(out + (size_t)b * OUTF)[tid] = r;
}

extern "C" void kernel_launch(void* const* d_in, const int* in_sizes, int n_in,
                              void* d_out, int out_size)
{
    const float* x      = (const float*)d_in[0];   // (B, 1024)
    const float* coeffs = (const float*)d_in[1];   // (1024, 7)
    const float* sigma  = (const float*)d_in[2];   // (1,)
    float* out          = (float*)d_out;           // (B, 1024)

    const int batch = in_sizes[0] / FEAT;          // 4096

    hermite_fused_kernel<<<batch, THREADS>>>(x, coeffs, sigma, out);
}

// round 2
// speedup vs baseline: 1.0951x; 1.0951x over previous
#include <cuda_runtime.h>

#define DEGREE   6
#define WIDTH    7          // DEGREE - START_DEGREE + 1
#define FEAT     1024       // in_features
#define OUTF     1024       // out_features
#define THREADS  256
#define NWARPS   (THREADS / 32)
#define GRID     592        // 148 SMs * 4 blocks

// Persistent fused kernel: each block grid-strides over batch rows.
// Coeffs (28 floats per thread, covering its 4 output columns) are loaded
// ONCE into registers and reused for every row -> kills the redundant
// per-block 28KB coeff reload that made R1 L1-bound.
__global__ __launch_bounds__(THREADS, 3)
void hermite_fused_kernel(const float* __restrict__ x,
                          const float* __restrict__ coeffs,
                          const float* __restrict__ sigma,
                          float* __restrict__ out,
                          int batch)
{
    __shared__ float s_part[NWARPS * WIDTH];
    __shared__ float s_basis[WIDTH];

    const int tid  = threadIdx.x;
    const int lane = tid & 31;
    const int warp = tid >> 5;

    // ---- one-time: sigma + register-resident coeffs ----
    const float s     = fminf(fmaxf(sigma[0], 0.1f), 5.0f);
    const float inv_s = 1.0f / s;

    // thread tid owns outputs [4*tid, 4*tid+3]; 28 contiguous floats of coeffs
    float4 c[7];
    {
        const float4* c4 =
            reinterpret_cast<const float4*>(coeffs + (size_t)(tid * 4) * WIDTH);
#pragma unroll
        for (int i = 0; i < 7; ++i) c[i] = c4[i];
    }
    const float* cf = reinterpret_cast<const float*>(c);

    for (int b = blockIdx.x; b < batch; b += GRID) {
        // ---- Phase 1: per-thread partial basis sums over 4 features ----
        const float4 xv =
            reinterpret_cast<const float4*>(x + (size_t)b * FEAT)[tid];
        const float xe[4] = { xv.x, xv.y, xv.z, xv.w };

        float acc[WIDTH];
#pragma unroll
        for (int w = 0; w < WIDTH; ++w) acc[w] = 0.0f;

#pragma unroll
        for (int e = 0; e < 4; ++e) {
            const float xs = xe[e] * inv_s;
            const float t  = fminf(xs * xs, 50.0f);
            const float g  = __expf(-t);

            float hm2 = 1.0f;          // H0
            float hm1 = 2.0f * xs;     // H1 (unclipped, as in reference)
            acc[0] += g;               // g * H0
            acc[1] += g * hm1;

            const float two_xs = 2.0f * xs;
#pragma unroll
            for (int n = 2; n <= DEGREE; ++n) {
                float h = two_xs * hm1 - (2.0f * (float)(n - 1)) * hm2;
                h = fminf(fmaxf(h, -100.0f), 100.0f);  // clip BEFORE recursion use
                acc[n] += g * h;
                hm2 = hm1;
                hm1 = h;
            }
        }

        // ---- Block reduction of the 7 accumulators ----
#pragma unroll
        for (int w = 0; w < WIDTH; ++w) {
#pragma unroll
            for (int off = 16; off > 0; off >>= 1)
                acc[w] += __shfl_xor_sync(0xffffffffu, acc[w], off);
        }
        if (lane == 0) {
#pragma unroll
            for (int w = 0; w < WIDTH; ++w)
                s_part[warp * WIDTH + w] = acc[w];
        }
        __syncthreads();

        if (tid < WIDTH) {
            float v = 0.0f;
#pragma unroll
            for (int ww = 0; ww < NWARPS; ++ww)
                v += s_part[ww * WIDTH + tid];
            s_basis[tid] = v;
        }
        __syncthreads();

        float basis[WIDTH];
#pragma unroll
        for (int w = 0; w < WIDTH; ++w) basis[w] = s_basis[w];

        // ---- Phase 2: 4 outputs per thread from register coeffs ----
        float4 r;
        float* rp = reinterpret_cast<float*>(&r);
#pragma unroll
        for (int i = 0; i < 4; ++i) {
            float v = 0.0f;
#pragma unroll
            for (int w = 0; w < WIDTH; ++w)
                v += basis[w] * cf[i * WIDTH + w];
            rp[i] = v;
        }
        reinterpret_cast<float4*>(out + (size_t)b * OUTF)[tid] = r;
    }
}

extern "C" void kernel_launch(void* const* d_in, const int* in_sizes, int n_in,
                              void* d_out, int out_size)
{
    const float* x      = (const float*)d_in[0];   // (B, 1024)
    const float* coeffs = (const float*)d_in[1];   // (1024, 7)
    const float* sigma  = (const float*)d_in[2];   // (1,)
    float* out          = (float*)d_out;           // (B, 1024)

    const int batch = in_sizes[0] / FEAT;          // 4096

    hermite_fused_kernel<<<GRID, THREADS>>>(x, coeffs, sigma, out, batch);
}

// round 3
// speedup vs baseline: 1.2909x; 1.1789x over previous
#include <cuda_runtime.h>

#define DEGREE   6
#define WIDTH    7          // DEGREE - START_DEGREE + 1
#define FEAT     1024       // in_features
#define OUTF     1024       // out_features
#define THREADS  256
#define ROWS_PER_BLOCK 8    // one row per warp

// Warp-per-row fused kernel:
//  - warp w of each block reduces batch row (blockIdx.x*8 + w) entirely with
//    warp shuffles (no __syncthreads on the reduction path)
//  - ONE barrier per block, then phase 2 computes 8 rows x 4 outputs/thread
//    from register-resident coeffs (loaded once, hidden behind phase 1)
__global__ __launch_bounds__(THREADS)
void hermite_fused_kernel(const float* __restrict__ x,
                          const float* __restrict__ coeffs,
                          const float* __restrict__ sigma,
                          float* __restrict__ out)
{
    __shared__ float s_basis[ROWS_PER_BLOCK][WIDTH];

    const int tid  = threadIdx.x;
    const int lane = tid & 31;
    const int warp = tid >> 5;

    // ---- issue coeff loads FIRST (consumed only after the barrier) ----
    // thread tid owns output columns [4*tid, 4*tid+3] -> 28 contiguous floats
    float4 c[7];
    {
        const float4* c4 =
            reinterpret_cast<const float4*>(coeffs + (size_t)(tid * 4) * WIDTH);
#pragma unroll
        for (int i = 0; i < 7; ++i) c[i] = c4[i];
    }

    const float s     = fminf(fmaxf(sigma[0], 0.1f), 5.0f);
    const float inv_s = 1.0f / s;

    // ---- Phase 1: this warp's row; 32 features per lane, front-batched ----
    const int b = blockIdx.x * ROWS_PER_BLOCK + warp;
    const float4* xr = reinterpret_cast<const float4*>(x + (size_t)b * FEAT);

    float4 xv[8];
#pragma unroll
    for (int i = 0; i < 8; ++i) xv[i] = xr[lane + 32 * i];

    float acc[WIDTH];
#pragma unroll
    for (int w = 0; w < WIDTH; ++w) acc[w] = 0.0f;

#pragma unroll
    for (int i = 0; i < 8; ++i) {
        const float xe[4] = { xv[i].x, xv[i].y, xv[i].z, xv[i].w };
#pragma unroll
        for (int e = 0; e < 4; ++e) {
            const float xs = xe[e] * inv_s;
            const float t  = fminf(xs * xs, 50.0f);
            const float g  = __expf(-t);

            float hm2 = 1.0f;          // H0
            float hm1 = 2.0f * xs;     // H1 (unclipped, as in reference)
            acc[0] += g;               // g * H0
            acc[1] += g * hm1;

            const float two_xs = 2.0f * xs;
#pragma unroll
            for (int n = 2; n <= DEGREE; ++n) {
                float h = two_xs * hm1 - (2.0f * (float)(n - 1)) * hm2;
                h = fminf(fmaxf(h, -100.0f), 100.0f);  // clip BEFORE recursion use
                acc[n] += g * h;
                hm2 = hm1;
                hm1 = h;
            }
        }
    }

    // ---- warp-local reduction of the 7 accumulators ----
#pragma unroll
    for (int w = 0; w < WIDTH; ++w) {
#pragma unroll
        for (int off = 16; off > 0; off >>= 1)
            acc[w] += __shfl_xor_sync(0xffffffffu, acc[w], off);
    }
    if (lane == 0) {
#pragma unroll
        for (int w = 0; w < WIDTH; ++w)
            s_basis[warp][w] = acc[w];
    }

    __syncthreads();   // the ONLY barrier

    // ---- Phase 2: 8 rows x 4 outputs per thread from register coeffs ----
    const float* cf = reinterpret_cast<const float*>(c);

#pragma unroll
    for (int r = 0; r < ROWS_PER_BLOCK; ++r) {
        float bs[WIDTH];
#pragma unroll
        for (int w = 0; w < WIDTH; ++w)
            bs[w] = s_basis[r][w];     // warp-uniform broadcast LDS

        float4 o;
        float* op = reinterpret_cast<float*>(&o);
#pragma unroll
        for (int i = 0; i < 4; ++i) {
            float v = 0.0f;
#pragma unroll
            for (int w = 0; w < WIDTH; ++w)
                v += bs[w] * cf[i * WIDTH + w];
            op[i] = v;
        }
        const int row = blockIdx.x * ROWS_PER_BLOCK + r;
        reinterpret_cast<float4*>(out + (size_t)row * OUTF)[tid] = o;
    }
}

extern "C" void kernel_launch(void* const* d_in, const int* in_sizes, int n_in,
                              void* d_out, int out_size)
{
    const float* x      = (const float*)d_in[0];   // (4096, 1024)
    const float* coeffs = (const float*)d_in[1];   // (1024, 7)
    const float* sigma  = (const float*)d_in[2];   // (1,)
    float* out          = (float*)d_out;           // (4096, 1024)

    const int batch  = in_sizes[0] / FEAT;         // 4096
    const int nblock = batch / ROWS_PER_BLOCK;     // 512

    hermite_fused_kernel<<<nblock, THREADS>>>(x, coeffs, sigma, out);
}

// round 4
// speedup vs baseline: 1.4681x; 1.1373x over previous
#include <cuda_runtime.h>

#define DEGREE   6
#define WIDTH    7          // DEGREE - START_DEGREE + 1
#define FEAT     1024       // in_features
#define OUTF     1024       // out_features
#define THREADS  256
#define NWARPS   8
#define ROWS_PER_BLOCK 4    // 2 warps per row -> 8192 warps total

// 2-warps-per-row fused kernel (occupancy fix for latency-bound profile):
//  - warp w handles row (blockIdx.x*4 + w/2), feature half (w&1): 512 feats,
//    16 per lane, 4x front-batched LDG.128, warp-shuffle reduce -> smem
//  - ONE barrier, then phase 2: each thread emits 4 rows x 4 outputs from
//    register-resident coeffs, summing the two half-row partials on the fly
__global__ __launch_bounds__(THREADS)
void hermite_fused_kernel(const float* __restrict__ x,
                          const float* __restrict__ coeffs,
                          const float* __restrict__ sigma,
                          float* __restrict__ out)
{
    __shared__ float s_part[NWARPS][WIDTH];

    const int tid  = threadIdx.x;
    const int lane = tid & 31;
    const int warp = tid >> 5;

    // ---- issue coeff loads FIRST (consumed only after the barrier) ----
    float4 c[7];
    {
        const float4* c4 =
            reinterpret_cast<const float4*>(coeffs + (size_t)(tid * 4) * WIDTH);
#pragma unroll
        for (int i = 0; i < 7; ++i) c[i] = c4[i];
    }

    const float s     = fminf(fmaxf(sigma[0], 0.1f), 5.0f);
    const float inv_s = 1.0f / s;

    // ---- Phase 1: half a row per warp (16 features/lane) ----
    const int row  = blockIdx.x * ROWS_PER_BLOCK + (warp >> 1);
    const int half = warp & 1;                         // which 512-feature half
    const float4* xr = reinterpret_cast<const float4*>(x + (size_t)row * FEAT)
                       + half * (FEAT / 8);            // 128 float4 per half

    float4 xv[4];
#pragma unroll
    for (int i = 0; i < 4; ++i) xv[i] = xr[lane + 32 * i];

    float acc[WIDTH];
#pragma unroll
    for (int w = 0; w < WIDTH; ++w) acc[w] = 0.0f;

#pragma unroll
    for (int i = 0; i < 4; ++i) {
        const float xe[4] = { xv[i].x, xv[i].y, xv[i].z, xv[i].w };
#pragma unroll
        for (int e = 0; e < 4; ++e) {
            const float xs = xe[e] * inv_s;
            // NOTE: min(xs*xs, 50) never binds for these inputs (t <= ~30);
            // even when it would, the difference is ~e-50 << 1e-3 tolerance.
            const float g  = __expf(-(xs * xs));

            float hm2 = 1.0f;          // H0
            float hm1 = 2.0f * xs;     // H1 (unclipped, as in reference)
            acc[0] += g;               // g * H0
            acc[1] += g * hm1;

            const float two_xs = 2.0f * xs;
#pragma unroll
            for (int n = 2; n <= DEGREE; ++n) {
                float h = two_xs * hm1 - (2.0f * (float)(n - 1)) * hm2;
                h = fminf(fmaxf(h, -100.0f), 100.0f);  // clip BEFORE recursion use
                acc[n] += g * h;
                hm2 = hm1;
                hm1 = h;
            }
        }
    }

    // ---- warp-local reduction of the 7 accumulators ----
#pragma unroll
    for (int w = 0; w < WIDTH; ++w) {
#pragma unroll
        for (int off = 16; off > 0; off >>= 1)
            acc[w] += __shfl_xor_sync(0xffffffffu, acc[w], off);
    }
    if (lane == 0) {
#pragma unroll
        for (int w = 0; w < WIDTH; ++w)
            s_part[warp][w] = acc[w];
    }

    __syncthreads();   // the ONLY barrier

    // ---- Phase 2: 4 rows x 4 outputs per thread from register coeffs ----
    const float* cf = reinterpret_cast<const float*>(c);

#pragma unroll
    for (int r = 0; r < ROWS_PER_BLOCK; ++r) {
        float bs[WIDTH];
#pragma unroll
        for (int w = 0; w < WIDTH; ++w)
            bs[w] = s_part[2 * r][w] + s_part[2 * r + 1][w];  // merge halves

        float4 o;
        float* op = reinterpret_cast<float*>(&o);
#pragma unroll
        for (int i = 0; i < 4; ++i) {
            float v = 0.0f;
#pragma unroll
            for (int w = 0; w < WIDTH; ++w)
                v += bs[w] * cf[i * WIDTH + w];
            op[i] = v;
        }
        const int orow = blockIdx.x * ROWS_PER_BLOCK + r;
        reinterpret_cast<float4*>(out + (size_t)orow * OUTF)[tid] = o;
    }
}

extern "C" void kernel_launch(void* const* d_in, const int* in_sizes, int n_in,
                              void* d_out, int out_size)
{
    const float* x      = (const float*)d_in[0];   // (4096, 1024)
    const float* coeffs = (const float*)d_in[1];   // (1024, 7)
    const float* sigma  = (const float*)d_in[2];   // (1,)
    float* out          = (float*)d_out;           // (4096, 1024)

    const int batch  = in_sizes[0] / FEAT;         // 4096
    const int nblock = batch / ROWS_PER_BLOCK;     // 1024

    hermite_fused_kernel<<<nblock, THREADS>>>(x, coeffs, sigma, out);
}